// round 8
// baseline (speedup 1.0000x reference)
#include <cuda_runtime.h>
#include <math.h>
#include <stdint.h>

// Problem shape (fixed)
#define T_DIM 2048
#define B_DIM 8
#define C_DIM 1024
#define H_DIM 16
#define K_DIM 7
#define R_DIM 64
#define M_DIM (T_DIM * B_DIM)        // 16384
#define NW    144
#define GK    1024

// Scratch (__device__ globals; allocation-free rule)
__device__ float g_P [(size_t)M_DIM * NW];     // GEMM1 out: logits + glu pre-act
__device__ float g_Y [(size_t)M_DIM * C_DIM];  // conv*gate result (tf32 bits)
__device__ float g_Xc[(size_t)M_DIM * C_DIM];  // x converted to tf32 bits
__device__ float g_W1[(size_t)NW * GK];        // [w_weight; glu_w] tf32 bits
__device__ float g_Wo[(size_t)C_DIM * GK];     // out_w tf32 bits

__device__ __forceinline__ uint32_t f2tf32(float f) {
    uint32_t u;
    asm("cvt.rna.tf32.f32 %0, %1;" : "=r"(u) : "f"(f));
    return u;
}
__device__ __forceinline__ uint32_t smem_addr(const void* p) {
    uint32_t a;
    asm("{ .reg .u64 t; cvta.to.shared.u64 t, %1; cvt.u32.u64 %0, t; }"
        : "=r"(a) : "l"(p));
    return a;
}

// ---------------------------------------------------------------------------
// Elementwise tf32 pre-conversion (vectorized x4)
// ---------------------------------------------------------------------------
__global__ __launch_bounds__(256) void cvt_tf32_kernel(
    const float4* __restrict__ src, float4* __restrict__ dst, int n4)
{
    const int i = blockIdx.x * blockDim.x + threadIdx.x;
    if (i < n4) {
        float4 v = src[i];
        float4 o;
        o.x = __uint_as_float(f2tf32(v.x));
        o.y = __uint_as_float(f2tf32(v.y));
        o.z = __uint_as_float(f2tf32(v.z));
        o.w = __uint_as_float(f2tf32(v.w));
        dst[i] = o;
    }
}

// ===========================================================================
// tf32 mma.sync GEMM (NT), cp.async double-buffered.
// Inputs are PRE-CONVERTED tf32 bit patterns (no cvt in hot loop).
// C[m*ldc+n] = sum_k A[m,k]*B[n,k] (+bias[n]).  M mult of 128, K=1024,
// N guarded (mult of 2 for paired stores).  Block 256 thr = 8 warps (2m x 4n),
// warp tile 64x32, 4x4 m16n8k8 frags, BK=32.
// Smem rows stride 36 u32 (144 B): 16B-aligned for cp.async chunks AND
// bank-conflict-free fragment gathers.
// ===========================================================================
#define STAGE_U32 9216                  // A(4608) + B(4608) u32 per stage
#define GEMM_SMEM (2 * STAGE_U32 * 4)   // 73728 B

__global__ __launch_bounds__(256, 2) void gemm_mma_tf32(
    const float* __restrict__ A, const float* __restrict__ B,
    const float* __restrict__ bias, float* __restrict__ C,
    int N, int ldc)
{
    extern __shared__ uint32_t sm[];
    const int tid  = threadIdx.x;
    const int lane = tid & 31;
    const int wid  = tid >> 5;
    const int warp_m = (wid >> 2) * 64;
    const int warp_n = (wid & 3) * 32;
    const int bm = blockIdx.y * 128;
    const int bn = blockIdx.x * 128;
    const uint32_t sbase = smem_addr(sm);

    float acc[4][4][4];
    #pragma unroll
    for (int i = 0; i < 4; ++i)
        #pragma unroll
        for (int j = 0; j < 4; ++j)
            #pragma unroll
            for (int q = 0; q < 4; ++q) acc[i][j][q] = 0.0f;

    const int r = lane >> 2;
    const int c = lane & 3;

    // ---- cp.async prefetch of one 128x32 A tile + B tile into a stage ----
    auto prefetch = [&](int kt, int stage) {
        const float* Ak = A + (size_t)bm * GK + kt * 32;
        const float* Bk = B + (size_t)bn * GK + kt * 32;
        const uint32_t abase = sbase + stage * (STAGE_U32 * 4);
        const uint32_t bbase = abase + 4608 * 4;
        #pragma unroll
        for (int i = 0; i < 4; ++i) {
            const int idx = tid + i * 256;        // 0..1023 chunks
            const int row = idx >> 3;             // 0..127
            const int ch  = idx & 7;              // 0..7 (16B chunks)
            const uint32_t dA = abase + row * 144 + ch * 16;
            const float* sA = Ak + (size_t)row * GK + ch * 4;
            asm volatile("cp.async.cg.shared.global [%0], [%1], 16;"
                         :: "r"(dA), "l"(sA));
            const uint32_t dB = bbase + row * 144 + ch * 16;
            const float* sB = Bk + (size_t)row * GK + ch * 4;
            const int ssz = (bn + row < N) ? 16 : 0;   // zero-fill OOB rows
            asm volatile("cp.async.cg.shared.global [%0], [%1], 16, %2;"
                         :: "r"(dB), "l"(sB), "r"(ssz));
        }
        asm volatile("cp.async.commit_group;" ::: "memory");
    };

    prefetch(0, 0);

    for (int kt = 0; kt < GK / 32; ++kt) {
        // Prefetch next tile into alternate stage (dup of last tile at the
        // end — harmless, keeps wait_group depth uniform).
        const int nkt = (kt + 1 < GK / 32) ? kt + 1 : GK / 32 - 1;
        prefetch(nkt, (kt + 1) & 1);
        asm volatile("cp.async.wait_group 1;" ::: "memory");
        __syncthreads();

        const uint32_t (*As)[36] =
            (const uint32_t(*)[36])(sm + (kt & 1) * STAGE_U32);
        const uint32_t (*Bs)[36] =
            (const uint32_t(*)[36])(sm + (kt & 1) * STAGE_U32 + 4608);

        #pragma unroll
        for (int ks = 0; ks < 4; ++ks) {
            const int kk = ks * 8;
            uint32_t a[4][4], b[4][2];
            #pragma unroll
            for (int i = 0; i < 4; ++i) {
                const int mr = warp_m + i * 16 + r;
                a[i][0] = As[mr][kk + c];
                a[i][1] = As[mr + 8][kk + c];
                a[i][2] = As[mr][kk + c + 4];
                a[i][3] = As[mr + 8][kk + c + 4];
            }
            #pragma unroll
            for (int j = 0; j < 4; ++j) {
                const int nr = warp_n + j * 8 + r;
                b[j][0] = Bs[nr][kk + c];
                b[j][1] = Bs[nr][kk + c + 4];
            }
            #pragma unroll
            for (int i = 0; i < 4; ++i)
                #pragma unroll
                for (int j = 0; j < 4; ++j)
                    asm volatile(
                        "mma.sync.aligned.m16n8k8.row.col.f32.tf32.tf32.f32 "
                        "{%0,%1,%2,%3}, {%4,%5,%6,%7}, {%8,%9}, {%0,%1,%2,%3};"
                        : "+f"(acc[i][j][0]), "+f"(acc[i][j][1]),
                          "+f"(acc[i][j][2]), "+f"(acc[i][j][3])
                        : "r"(a[i][0]), "r"(a[i][1]), "r"(a[i][2]), "r"(a[i][3]),
                          "r"(b[j][0]), "r"(b[j][1]));
        }
        __syncthreads();   // protect stage being overwritten next iteration
    }

    // ---- epilogue ----
    const int c2 = c * 2;
    #pragma unroll
    for (int i = 0; i < 4; ++i) {
        const int m0 = bm + warp_m + i * 16 + r;
        #pragma unroll
        for (int j = 0; j < 4; ++j) {
            const int n = bn + warp_n + j * 8 + c2;
            if (n < N) {
                const float b0v = bias ? bias[n]     : 0.0f;
                const float b1v = bias ? bias[n + 1] : 0.0f;
                float2 v0 = make_float2(acc[i][j][0] + b0v, acc[i][j][1] + b1v);
                float2 v1 = make_float2(acc[i][j][2] + b0v, acc[i][j][3] + b1v);
                *(float2*)(C + (size_t)m0 * ldc + n)       = v0;
                *(float2*)(C + (size_t)(m0 + 8) * ldc + n) = v1;
            }
        }
    }
}

// ===========================================================================
// Middle stage: one warp per (t,b,h): softmax(K=7) + GLU gate + depthwise
// dynamic conv. Writes Y PRE-CONVERTED to tf32 bits (GEMM2 input).
// ===========================================================================
__global__ __launch_bounds__(256) void conv_gate_kernel(
    const float* __restrict__ x, const float* __restrict__ glu_b,
    const int* __restrict__ pad_p)
{
    const int warp = (blockIdx.x * blockDim.x + threadIdx.x) >> 5;
    const int lane = threadIdx.x & 31;
    if (warp >= M_DIM * H_DIM) return;

    const int h  = warp % H_DIM;
    const int m  = warp / H_DIM;
    const int b  = m % B_DIM;
    const int t  = m / B_DIM;
    const int pad = pad_p ? *pad_p : 6;

    const float* Prow = g_P + (size_t)m * NW;

    float lg[K_DIM];
    #pragma unroll
    for (int k = 0; k < K_DIM; ++k) lg[k] = Prow[h * K_DIM + k];
    float mx = lg[0];
    #pragma unroll
    for (int k = 1; k < K_DIM; ++k) mx = fmaxf(mx, lg[k]);
    float s = 0.0f;
    #pragma unroll
    for (int k = 0; k < K_DIM; ++k) { lg[k] = expf(lg[k] - mx); s += lg[k]; }
    const float inv = 1.0f / s;
    #pragma unroll
    for (int k = 0; k < K_DIM; ++k) lg[k] *= inv;

    const float ga = Prow[112 + 2 * h]     + glu_b[2 * h];
    const float gb = Prow[112 + 2 * h + 1] + glu_b[2 * h + 1];
    const float gate = ga / (1.0f + expf(-gb));

    const int base_c = h * R_DIM;
    #pragma unroll
    for (int rr = 0; rr < 2; ++rr) {
        const int r = lane + rr * 32;
        float accv = 0.0f;
        #pragma unroll
        for (int k = 0; k < K_DIM; ++k) {
            const int st = t + k - pad;
            if (st >= 0 && st < T_DIM) {
                accv = fmaf(lg[k],
                            x[((size_t)st * B_DIM + b) * C_DIM + base_c + r],
                            accv);
            }
        }
        g_Y[(size_t)m * C_DIM + base_c + r] =
            __uint_as_float(f2tf32(accv * gate));
    }
}

// ===========================================================================
// Launch
// ===========================================================================
extern "C" void kernel_launch(void* const* d_in, const int* in_sizes, int n_in,
                              void* d_out, int out_size)
{
    const float* x        = (const float*)d_in[0];
    const float* w_weight = (const float*)d_in[1];
    const float* glu_w    = (const float*)d_in[2];
    const float* glu_b    = (const float*)d_in[3];
    const float* out_w    = (const float*)d_in[4];
    const float* out_b    = (const float*)d_in[5];
    const int*   pad_p    = (n_in > 6) ? (const int*)d_in[6] : nullptr;

    float *P, *Y, *Xc, *W1, *Wo;
    cudaGetSymbolAddress((void**)&P,  g_P);
    cudaGetSymbolAddress((void**)&Y,  g_Y);
    cudaGetSymbolAddress((void**)&Xc, g_Xc);
    cudaGetSymbolAddress((void**)&W1, g_W1);
    cudaGetSymbolAddress((void**)&Wo, g_Wo);

    cudaFuncSetAttribute(gemm_mma_tf32,
                         cudaFuncAttributeMaxDynamicSharedMemorySize, GEMM_SMEM);

    // tf32 pre-conversion (weights + x)
    {
        int n4 = (112 * GK) / 4;
        cvt_tf32_kernel<<<(n4 + 255) / 256, 256>>>(
            (const float4*)w_weight, (float4*)W1, n4);
    }
    {
        int n4 = (32 * GK) / 4;
        cvt_tf32_kernel<<<(n4 + 255) / 256, 256>>>(
            (const float4*)glu_w, (float4*)(W1 + (size_t)112 * GK), n4);
    }
    {
        int n4 = (C_DIM * GK) / 4;
        cvt_tf32_kernel<<<(n4 + 255) / 256, 256>>>(
            (const float4*)out_w, (float4*)Wo, n4);
    }
    {
        int n4 = (M_DIM * C_DIM) / 4;
        cvt_tf32_kernel<<<(n4 + 255) / 256, 256>>>(
            (const float4*)x, (float4*)Xc, n4);
    }

    // GEMM1 (combined): P = Xc @ [w_weight; glu_w]^T   (N=144)
    gemm_mma_tf32<<<dim3(2, M_DIM / 128), 256, GEMM_SMEM>>>(
        Xc, W1, nullptr, P, NW, NW);

    // Middle stage (reads fp32 x, writes tf32 Y)
    {
        const int total_warps = M_DIM * H_DIM;
        const int blocks = (total_warps * 32 + 255) / 256;
        conv_gate_kernel<<<blocks, 256>>>(x, glu_b, pad_p);
    }

    // GEMM2: out = Y @ out_w^T + out_b   (N=1024)
    gemm_mma_tf32<<<dim3(C_DIM / 128, M_DIM / 128), 256, GEMM_SMEM>>>(
        Y, Wo, out_b, (float*)d_out, C_DIM, C_DIM);
}

// round 10
// speedup vs baseline: 1.5578x; 1.5578x over previous
#include <cuda_runtime.h>
#include <math.h>
#include <stdint.h>

// Problem shape (fixed)
#define T_DIM 2048
#define B_DIM 8
#define C_DIM 1024
#define H_DIM 16
#define K_DIM 7
#define R_DIM 64
#define M_DIM (T_DIM * B_DIM)        // 16384
#define NW    144
#define GK    1024
#define KT    (GK / 32)              // 32 k-tiles

// Scratch (__device__ globals; allocation-free rule)
__device__ float g_P [(size_t)M_DIM * NW];     // GEMM1 out: logits + glu pre-act
__device__ float g_Y [(size_t)M_DIM * C_DIM];  // conv*gate result
__device__ float g_W1[(size_t)NW * GK];        // [w_weight; glu_w] concatenated

__device__ __forceinline__ uint32_t f2tf32(float f) {
    uint32_t u;
    asm("cvt.rna.tf32.f32 %0, %1;" : "=r"(u) : "f"(f));
    return u;
}

// ===========================================================================
// tf32 mma.sync GEMM (NT), register-staged double-buffered smem.
// C[m*ldc+n] = sum_k A[m,k]*B[n,k] (+bias[n]).  M mult of 128, K=1024,
// N guarded.  256 thr = 8 warps (2m x 4n), warp tile 64x32, 4x4 m16n8k8,
// BK=32.  Smem rows stride 36 u32: bank-conflict-free fragment gathers,
// 16B-aligned rows for STS.128.  ONE __syncthreads per k-tile.
// ===========================================================================
#define STAGE_U32 9216                    // A(128*36) + B(128*36) per stage
#define GEMM_SMEM (2 * STAGE_U32 * 4)     // 73728 B dynamic

__global__ __launch_bounds__(256) void gemm_mma_tf32(
    const float* __restrict__ A, const float* __restrict__ B,
    const float* __restrict__ bias, float* __restrict__ C,
    int N, int ldc)
{
    extern __shared__ uint32_t sm[];
    const int tid  = threadIdx.x;
    const int lane = tid & 31;
    const int wid  = tid >> 5;
    const int warp_m = (wid >> 2) * 64;
    const int warp_n = (wid & 3) * 32;
    const int bm = blockIdx.y * 128;
    const int bn = blockIdx.x * 128;

    float acc[4][4][4];
    #pragma unroll
    for (int i = 0; i < 4; ++i)
        #pragma unroll
        for (int j = 0; j < 4; ++j)
            #pragma unroll
            for (int q = 0; q < 4; ++q) acc[i][j][q] = 0.0f;

    const int r = lane >> 2;
    const int c = lane & 3;

    // per-thread staging registers (tile k+1 in flight during compute of k)
    float4 avr[4], bvr[4];

    const int ld_row = tid >> 3;            // wrong-free helpers computed once
    // NOTE: each thread covers idx = tid + i*256 -> row = idx>>3, c4 = (idx&7)*4
    // Since i*256 is a multiple of 256, row = (tid>>3) + i*32, c4 fixed per thread.
    const int ld_c4  = (tid & 7) * 4;

    auto ldg = [&](int kt) {
        const float* Ak = A + (size_t)bm * GK + kt * 32 + ld_c4;
        const float* Bk = B + (size_t)bn * GK + kt * 32 + ld_c4;
        #pragma unroll
        for (int i = 0; i < 4; ++i) {
            const int row = ld_row + i * 32;
            avr[i] = *(const float4*)(Ak + (size_t)row * GK);
            if (bn + row < N)
                bvr[i] = *(const float4*)(Bk + (size_t)row * GK);
            else
                bvr[i] = make_float4(0.f, 0.f, 0.f, 0.f);
        }
    };
    auto sts = [&](int s) {
        uint32_t* dst = sm + s * STAGE_U32;
        #pragma unroll
        for (int i = 0; i < 4; ++i) {
            const int row = ld_row + i * 32;
            uint4 a4, b4;
            a4.x = f2tf32(avr[i].x); a4.y = f2tf32(avr[i].y);
            a4.z = f2tf32(avr[i].z); a4.w = f2tf32(avr[i].w);
            b4.x = f2tf32(bvr[i].x); b4.y = f2tf32(bvr[i].y);
            b4.z = f2tf32(bvr[i].z); b4.w = f2tf32(bvr[i].w);
            *(uint4*)(dst + row * 36 + ld_c4)        = a4;
            *(uint4*)(dst + 4608 + row * 36 + ld_c4) = b4;
        }
    };

    ldg(0);
    sts(0);

    for (int kt = 0; kt < KT; ++kt) {
        __syncthreads();                    // stage kt&1 fully written
        if (kt + 1 < KT) ldg(kt + 1);       // LDG overlaps compute below

        const uint32_t* As_ = sm + (kt & 1) * STAGE_U32;
        const uint32_t* Bs_ = As_ + 4608;

        #pragma unroll
        for (int ks = 0; ks < 4; ++ks) {
            const int kk = ks * 8;
            uint32_t a[4][4], b[4][2];
            #pragma unroll
            for (int i = 0; i < 4; ++i) {
                const int mr = warp_m + i * 16 + r;
                a[i][0] = As_[mr * 36 + kk + c];
                a[i][1] = As_[(mr + 8) * 36 + kk + c];
                a[i][2] = As_[mr * 36 + kk + c + 4];
                a[i][3] = As_[(mr + 8) * 36 + kk + c + 4];
            }
            #pragma unroll
            for (int j = 0; j < 4; ++j) {
                const int nr = warp_n + j * 8 + r;
                b[j][0] = Bs_[nr * 36 + kk + c];
                b[j][1] = Bs_[nr * 36 + kk + c + 4];
            }
            #pragma unroll
            for (int i = 0; i < 4; ++i)
                #pragma unroll
                for (int j = 0; j < 4; ++j)
                    asm volatile(
                        "mma.sync.aligned.m16n8k8.row.col.f32.tf32.tf32.f32 "
                        "{%0,%1,%2,%3}, {%4,%5,%6,%7}, {%8,%9}, {%0,%1,%2,%3};"
                        : "+f"(acc[i][j][0]), "+f"(acc[i][j][1]),
                          "+f"(acc[i][j][2]), "+f"(acc[i][j][3])
                        : "r"(a[i][0]), "r"(a[i][1]), "r"(a[i][2]), "r"(a[i][3]),
                          "r"(b[j][0]), "r"(b[j][1]));
        }

        if (kt + 1 < KT) sts((kt + 1) & 1); // write the OTHER stage; safe:
                                            // all warps passed sync of this
                                            // iter => done computing kt-1
    }

    // ---- epilogue: paired f32x2 stores, guarded on N ----
    const int c2 = c * 2;
    #pragma unroll
    for (int i = 0; i < 4; ++i) {
        const int m0 = bm + warp_m + i * 16 + r;
        #pragma unroll
        for (int j = 0; j < 4; ++j) {
            const int n = bn + warp_n + j * 8 + c2;
            if (n < N) {
                const float b0v = bias ? bias[n]     : 0.0f;
                const float b1v = bias ? bias[n + 1] : 0.0f;
                float2 v0 = make_float2(acc[i][j][0] + b0v, acc[i][j][1] + b1v);
                float2 v1 = make_float2(acc[i][j][2] + b0v, acc[i][j][3] + b1v);
                *(float2*)(C + (size_t)m0 * ldc + n)       = v0;
                *(float2*)(C + (size_t)(m0 + 8) * ldc + n) = v1;
            }
        }
    }
}

// ===========================================================================
// Middle stage: one warp per (t,b,h): softmax(K=7) + GLU gate + depthwise
// dynamic conv.
// ===========================================================================
__global__ __launch_bounds__(256) void conv_gate_kernel(
    const float* __restrict__ x, const float* __restrict__ glu_b,
    const int* __restrict__ pad_p)
{
    const int warp = (blockIdx.x * blockDim.x + threadIdx.x) >> 5;
    const int lane = threadIdx.x & 31;
    if (warp >= M_DIM * H_DIM) return;

    const int h  = warp % H_DIM;
    const int m  = warp / H_DIM;
    const int b  = m % B_DIM;
    const int t  = m / B_DIM;
    const int pad = pad_p ? *pad_p : 6;

    const float* Prow = g_P + (size_t)m * NW;

    float lg[K_DIM];
    #pragma unroll
    for (int k = 0; k < K_DIM; ++k) lg[k] = Prow[h * K_DIM + k];
    float mx = lg[0];
    #pragma unroll
    for (int k = 1; k < K_DIM; ++k) mx = fmaxf(mx, lg[k]);
    float s = 0.0f;
    #pragma unroll
    for (int k = 0; k < K_DIM; ++k) { lg[k] = expf(lg[k] - mx); s += lg[k]; }
    const float inv = 1.0f / s;
    #pragma unroll
    for (int k = 0; k < K_DIM; ++k) lg[k] *= inv;

    const float ga = Prow[112 + 2 * h]     + glu_b[2 * h];
    const float gb = Prow[112 + 2 * h + 1] + glu_b[2 * h + 1];
    const float gate = ga / (1.0f + expf(-gb));

    const int base_c = h * R_DIM;
    #pragma unroll
    for (int rr = 0; rr < 2; ++rr) {
        const int r = lane + rr * 32;
        float accv = 0.0f;
        #pragma unroll
        for (int k = 0; k < K_DIM; ++k) {
            const int st = t + k - pad;
            if (st >= 0 && st < T_DIM) {
                accv = fmaf(lg[k],
                            x[((size_t)st * B_DIM + b) * C_DIM + base_c + r],
                            accv);
            }
        }
        g_Y[(size_t)m * C_DIM + base_c + r] = accv * gate;
    }
}

// ===========================================================================
// Launch
// ===========================================================================
extern "C" void kernel_launch(void* const* d_in, const int* in_sizes, int n_in,
                              void* d_out, int out_size)
{
    const float* x        = (const float*)d_in[0];
    const float* w_weight = (const float*)d_in[1];
    const float* glu_w    = (const float*)d_in[2];
    const float* glu_b    = (const float*)d_in[3];
    const float* out_w    = (const float*)d_in[4];
    const float* out_b    = (const float*)d_in[5];
    const int*   pad_p    = (n_in > 6) ? (const int*)d_in[6] : nullptr;

    float *P, *Y, *W1;
    cudaGetSymbolAddress((void**)&P,  g_P);
    cudaGetSymbolAddress((void**)&Y,  g_Y);
    cudaGetSymbolAddress((void**)&W1, g_W1);

    cudaFuncSetAttribute(gemm_mma_tf32,
                         cudaFuncAttributeMaxDynamicSharedMemorySize, GEMM_SMEM);

    // Concat weights for merged GEMM1 (D2D copies; graph-capturable)
    cudaMemcpyAsync(W1, w_weight, (size_t)112 * GK * sizeof(float),
                    cudaMemcpyDeviceToDevice, 0);
    cudaMemcpyAsync(W1 + (size_t)112 * GK, glu_w, (size_t)32 * GK * sizeof(float),
                    cudaMemcpyDeviceToDevice, 0);

    // GEMM1 (merged): P = x @ [w_weight; glu_w]^T   (N=144)
    gemm_mma_tf32<<<dim3(2, M_DIM / 128), 256, GEMM_SMEM>>>(
        x, W1, nullptr, P, NW, NW);

    // Middle stage
    {
        const int total_warps = M_DIM * H_DIM;
        const int blocks = (total_warps * 32 + 255) / 256;
        conv_gate_kernel<<<blocks, 256>>>(x, glu_b, pad_p);
    }

    // GEMM2: out = Y @ out_w^T + out_b   (N=1024)
    gemm_mma_tf32<<<dim3(C_DIM / 128, M_DIM / 128), 256, GEMM_SMEM>>>(
        Y, out_w, out_b, (float*)d_out, C_DIM, C_DIM);
}

// round 11
// speedup vs baseline: 1.6636x; 1.0679x over previous
#include <cuda_runtime.h>
#include <math.h>
#include <stdint.h>

// Problem shape (fixed)
#define T_DIM 2048
#define B_DIM 8
#define C_DIM 1024
#define H_DIM 16
#define K_DIM 7
#define R_DIM 64
#define M_DIM (T_DIM * B_DIM)        // 16384
#define NW    144
#define GK    1024
#define KT    (GK / 32)              // 32 k-tiles

// Scratch (__device__ globals; allocation-free rule)
__device__ float g_P [(size_t)M_DIM * NW];     // GEMM1 out: logits + glu pre-act
__device__ float g_Y [(size_t)M_DIM * C_DIM];  // conv*gate result
__device__ float g_W1[(size_t)NW * GK];        // [w_weight; glu_w] concatenated

__device__ __forceinline__ uint32_t f2tf32(float f) {
    uint32_t u;
    asm("cvt.rna.tf32.f32 %0, %1;" : "=r"(u) : "f"(f));
    return u;
}

// ===========================================================================
// tf32 mma.sync GEMM (NT): register-staged smem double buffering (global
// level) + fragment double buffering (smem->reg level).
// C[m*ldc+n] = sum_k A[m,k]*B[n,k] (+bias[n]).  M mult of 128, K=1024.
// 256 thr = 8 warps (2m x 4n), warp tile 64x32, 4x4 m16n8k8, BK=32.
// Smem rows stride 36 u32: conflict-free gathers, 16B-aligned STS.128.
// ===========================================================================
#define STAGE_U32 9216                    // A(128*36) + B(128*36) per stage
#define GEMM_SMEM (2 * STAGE_U32 * 4)     // 73728 B dynamic

__global__ __launch_bounds__(256) void gemm_mma_tf32(
    const float* __restrict__ A, const float* __restrict__ B,
    const float* __restrict__ bias, float* __restrict__ C,
    int N, int ldc)
{
    extern __shared__ uint32_t sm[];
    const int tid  = threadIdx.x;
    const int lane = tid & 31;
    const int wid  = tid >> 5;
    const int warp_m = (wid >> 2) * 64;
    const int warp_n = (wid & 3) * 32;
    const int bm = blockIdx.y * 128;
    const int bn = blockIdx.x * 128;

    float acc[4][4][4];
    #pragma unroll
    for (int i = 0; i < 4; ++i)
        #pragma unroll
        for (int j = 0; j < 4; ++j)
            #pragma unroll
            for (int q = 0; q < 4; ++q) acc[i][j][q] = 0.0f;

    const int r = lane >> 2;
    const int c = lane & 3;

    // global->register staging (tile kt+1 in flight during compute of kt)
    float4 avr[4], bvr[4];
    const int ld_row = tid >> 3;
    const int ld_c4  = (tid & 7) * 4;

    auto ldg = [&](int kt) {
        const float* Ak = A + (size_t)bm * GK + kt * 32 + ld_c4;
        const float* Bk = B + (size_t)bn * GK + kt * 32 + ld_c4;
        #pragma unroll
        for (int i = 0; i < 4; ++i) {
            const int row = ld_row + i * 32;
            avr[i] = *(const float4*)(Ak + (size_t)row * GK);
            if (bn + row < N)
                bvr[i] = *(const float4*)(Bk + (size_t)row * GK);
            else
                bvr[i] = make_float4(0.f, 0.f, 0.f, 0.f);
        }
    };
    auto sts = [&](int s) {
        uint32_t* dst = sm + s * STAGE_U32;
        #pragma unroll
        for (int i = 0; i < 4; ++i) {
            const int row = ld_row + i * 32;
            uint4 a4, b4;
            a4.x = f2tf32(avr[i].x); a4.y = f2tf32(avr[i].y);
            a4.z = f2tf32(avr[i].z); a4.w = f2tf32(avr[i].w);
            b4.x = f2tf32(bvr[i].x); b4.y = f2tf32(bvr[i].y);
            b4.z = f2tf32(bvr[i].z); b4.w = f2tf32(bvr[i].w);
            *(uint4*)(dst + row * 36 + ld_c4)        = a4;
            *(uint4*)(dst + 4608 + row * 36 + ld_c4) = b4;
        }
    };

    // smem->register fragment double buffer
    uint32_t afr[2][4][4], bfr[2][4][2];

    ldg(0);
    sts(0);

    for (int kt = 0; kt < KT; ++kt) {
        __syncthreads();                    // stage kt&1 fully written
        if (kt + 1 < KT) ldg(kt + 1);       // global prefetch overlaps MMAs

        const uint32_t* As_ = sm + (kt & 1) * STAGE_U32;
        const uint32_t* Bs_ = As_ + 4608;
        const uint32_t* aBase = As_ + (warp_m + r) * 36 + c;
        const uint32_t* bBase = Bs_ + (warp_n + r) * 36 + c;

        // preload fragments for ks=0
        #pragma unroll
        for (int i = 0; i < 4; ++i) {
            const uint32_t* p = aBase + i * (16 * 36);
            afr[0][i][0] = p[0];
            afr[0][i][1] = p[8 * 36];
            afr[0][i][2] = p[4];
            afr[0][i][3] = p[8 * 36 + 4];
        }
        #pragma unroll
        for (int j = 0; j < 4; ++j) {
            const uint32_t* p = bBase + j * (8 * 36);
            bfr[0][j][0] = p[0];
            bfr[0][j][1] = p[4];
        }

        #pragma unroll
        for (int ks = 0; ks < 4; ++ks) {
            const int cur = ks & 1;
            if (ks < 3) {                   // prefetch fragments for ks+1
                const int nxt = cur ^ 1;
                const int kk = (ks + 1) * 8;
                #pragma unroll
                for (int i = 0; i < 4; ++i) {
                    const uint32_t* p = aBase + i * (16 * 36) + kk;
                    afr[nxt][i][0] = p[0];
                    afr[nxt][i][1] = p[8 * 36];
                    afr[nxt][i][2] = p[4];
                    afr[nxt][i][3] = p[8 * 36 + 4];
                }
                #pragma unroll
                for (int j = 0; j < 4; ++j) {
                    const uint32_t* p = bBase + j * (8 * 36) + kk;
                    bfr[nxt][j][0] = p[0];
                    bfr[nxt][j][1] = p[4];
                }
            }
            #pragma unroll
            for (int i = 0; i < 4; ++i)
                #pragma unroll
                for (int j = 0; j < 4; ++j)
                    asm volatile(
                        "mma.sync.aligned.m16n8k8.row.col.f32.tf32.tf32.f32 "
                        "{%0,%1,%2,%3}, {%4,%5,%6,%7}, {%8,%9}, {%0,%1,%2,%3};"
                        : "+f"(acc[i][j][0]), "+f"(acc[i][j][1]),
                          "+f"(acc[i][j][2]), "+f"(acc[i][j][3])
                        : "r"(afr[cur][i][0]), "r"(afr[cur][i][1]),
                          "r"(afr[cur][i][2]), "r"(afr[cur][i][3]),
                          "r"(bfr[cur][j][0]), "r"(bfr[cur][j][1]));
        }

        if (kt + 1 < KT) sts((kt + 1) & 1); // write other stage (safe: that
                                            // stage last read in iter kt-1,
                                            // all threads passed this sync)
    }

    // ---- epilogue: paired f32x2 stores, guarded on N ----
    const int c2 = c * 2;
    #pragma unroll
    for (int i = 0; i < 4; ++i) {
        const int m0 = bm + warp_m + i * 16 + r;
        #pragma unroll
        for (int j = 0; j < 4; ++j) {
            const int n = bn + warp_n + j * 8 + c2;
            if (n < N) {
                const float b0v = bias ? bias[n]     : 0.0f;
                const float b1v = bias ? bias[n + 1] : 0.0f;
                float2 v0 = make_float2(acc[i][j][0] + b0v, acc[i][j][1] + b1v);
                float2 v1 = make_float2(acc[i][j][2] + b0v, acc[i][j][3] + b1v);
                *(float2*)(C + (size_t)m0 * ldc + n)       = v0;
                *(float2*)(C + (size_t)(m0 + 8) * ldc + n) = v1;
            }
        }
    }
}

// ===========================================================================
// Tiled middle stage: block = (t-tile of 64) x (b) x (h).
// Stage x tile (+12 halo rows) in smem once; softmax/gate in smem; each
// thread computes 16 (t,r) outputs. x traffic drops ~7x vs naive version.
// ===========================================================================
#define CT 64                     // t-tile
#define XROWS (CT + 12)           // halo: 6 left + 6 right (any pad 0..6)

__global__ __launch_bounds__(256) void conv_gate_tiled(
    const float* __restrict__ x, const float* __restrict__ glu_b,
    const int* __restrict__ pad_p)
{
    __shared__ float xs[XROWS * R_DIM];     // 19456 B
    __shared__ float ws[CT][8];             // softmax weights per t
    __shared__ float gs[CT];                // gate per t

    const int t0 = blockIdx.x * CT;
    const int b  = blockIdx.y;
    const int h  = blockIdx.z;
    const int tid = threadIdx.x;
    const int pad = pad_p ? *pad_p : 6;
    const int base_c = h * R_DIM;

    // load x rows [t0-6, t0+63+6] for channels [base_c, base_c+64)
    for (int i = tid; i < XROWS * R_DIM; i += 256) {
        const int row = i >> 6;
        const int r   = i & 63;
        const int t   = t0 - 6 + row;
        float v = 0.0f;
        if (t >= 0 && t < T_DIM)
            v = x[((size_t)t * B_DIM + b) * C_DIM + base_c + r];
        xs[i] = v;
    }

    // softmax + gate for this block's 64 t values (threads 0..63)
    if (tid < CT) {
        const int t = t0 + tid;
        const int m = t * B_DIM + b;
        const float* Prow = g_P + (size_t)m * NW;
        float lg[K_DIM];
        #pragma unroll
        for (int k = 0; k < K_DIM; ++k) lg[k] = Prow[h * K_DIM + k];
        float mx = lg[0];
        #pragma unroll
        for (int k = 1; k < K_DIM; ++k) mx = fmaxf(mx, lg[k]);
        float s = 0.0f;
        #pragma unroll
        for (int k = 0; k < K_DIM; ++k) { lg[k] = expf(lg[k] - mx); s += lg[k]; }
        const float inv = 1.0f / s;
        #pragma unroll
        for (int k = 0; k < K_DIM; ++k) ws[tid][k] = lg[k] * inv;

        const float ga = Prow[112 + 2 * h]     + glu_b[2 * h];
        const float gb = Prow[112 + 2 * h + 1] + glu_b[2 * h + 1];
        gs[tid] = ga / (1.0f + expf(-gb));
    }
    __syncthreads();

    // compute: thread -> (r = tid&63, tg = tid>>6); 16 t's per thread
    const int r  = tid & 63;
    const int tg = tid >> 6;
    const int hoff = 6 - pad;               // smem row offset for k=0
    #pragma unroll
    for (int i = 0; i < 16; ++i) {
        const int tt = tg * 16 + i;
        float accv = 0.0f;
        #pragma unroll
        for (int k = 0; k < K_DIM; ++k)
            accv = fmaf(ws[tt][k], xs[(tt + k + hoff) * R_DIM + r], accv);
        const int m = (t0 + tt) * B_DIM + b;
        g_Y[(size_t)m * C_DIM + base_c + r] = accv * gs[tt];
    }
}

// ===========================================================================
// Launch
// ===========================================================================
extern "C" void kernel_launch(void* const* d_in, const int* in_sizes, int n_in,
                              void* d_out, int out_size)
{
    const float* x        = (const float*)d_in[0];
    const float* w_weight = (const float*)d_in[1];
    const float* glu_w    = (const float*)d_in[2];
    const float* glu_b    = (const float*)d_in[3];
    const float* out_w    = (const float*)d_in[4];
    const float* out_b    = (const float*)d_in[5];
    const int*   pad_p    = (n_in > 6) ? (const int*)d_in[6] : nullptr;

    float *P, *Y, *W1;
    cudaGetSymbolAddress((void**)&P,  g_P);
    cudaGetSymbolAddress((void**)&Y,  g_Y);
    cudaGetSymbolAddress((void**)&W1, g_W1);

    cudaFuncSetAttribute(gemm_mma_tf32,
                         cudaFuncAttributeMaxDynamicSharedMemorySize, GEMM_SMEM);

    // Concat weights for merged GEMM1 (D2D, graph-capturable)
    cudaMemcpyAsync(W1, w_weight, (size_t)112 * GK * sizeof(float),
                    cudaMemcpyDeviceToDevice, 0);
    cudaMemcpyAsync(W1 + (size_t)112 * GK, glu_w, (size_t)32 * GK * sizeof(float),
                    cudaMemcpyDeviceToDevice, 0);

    // GEMM1 (merged): P = x @ [w_weight; glu_w]^T   (N=144)
    gemm_mma_tf32<<<dim3(2, M_DIM / 128), 256, GEMM_SMEM>>>(
        x, W1, nullptr, P, NW, NW);

    // Middle stage (tiled)
    conv_gate_tiled<<<dim3(T_DIM / CT, B_DIM, H_DIM), 256>>>(x, glu_b, pad_p);

    // GEMM2: out = Y @ out_w^T + out_b   (N=1024)
    gemm_mma_tf32<<<dim3(C_DIM / 128, M_DIM / 128), 256, GEMM_SMEM>>>(
        Y, out_w, out_b, (float*)d_out, C_DIM, C_DIM);
}

// round 12
// speedup vs baseline: 1.6819x; 1.0110x over previous
#include <cuda_runtime.h>
#include <math.h>
#include <stdint.h>

// Problem shape (fixed)
#define T_DIM 2048
#define B_DIM 8
#define C_DIM 1024
#define H_DIM 16
#define K_DIM 7
#define R_DIM 64
#define M_DIM (T_DIM * B_DIM)        // 16384
#define NW    144
#define GK    1024
#define KT    (GK / 32)              // 32 k-tiles

// Scratch (__device__ globals; allocation-free rule)
__device__ float g_P [(size_t)M_DIM * NW];     // GEMM1 out: logits + glu pre-act
__device__ float g_Y [(size_t)M_DIM * C_DIM];  // conv*gate result
__device__ float g_W1[(size_t)NW * GK];        // [w_weight; glu_w] concatenated

__device__ __forceinline__ uint32_t f2tf32(float f) {
    uint32_t u;
    asm("cvt.rna.tf32.f32 %0, %1;" : "=r"(u) : "f"(f));
    return u;
}

// ===========================================================================
// tf32 mma.sync GEMM (NT) with FRAGMENT-PERMUTED smem layout.
// C[m*ldc+n] = sum_k A[m,k]*B[n,k] (+bias[n]).  M mult of 128, K=1024.
// 256 thr = 8 warps (2m x 4n), warp tile 64x32, 4x4 m16n8k8, BK=32.
//
// Smem layout per stage:
//   A: 32 frags (mi 0..7 x ki 0..3), frag = [lane][4 regs], stride 132 u32
//      (132 mod 32 = 4 -> STS scatter spreads banks; LDS.128 conflict-free)
//   B: 64 frags (nb 0..15 x ki 0..3), frag = [lane][2 regs], stride 68 u32
// Gather: A = 4x LDS.128, B = 4x LDS.64 per ks (was 24x LDS.32).
// ===========================================================================
#define A_REG_U32 4224                    // 32 * 132
#define STAGE_U32 8576                    // A(4224) + B(64*68 = 4352)
#define GEMM_SMEM (2 * STAGE_U32 * 4)     // 68608 B dynamic

__global__ __launch_bounds__(256, 2) void gemm_mma_tf32(
    const float* __restrict__ A, const float* __restrict__ B,
    const float* __restrict__ bias, float* __restrict__ C,
    int N, int ldc)
{
    extern __shared__ uint32_t sm[];
    const int tid  = threadIdx.x;
    const int lane = tid & 31;
    const int wid  = tid >> 5;
    const int warp_m = (wid >> 2) * 64;
    const int warp_n = (wid & 3) * 32;
    const int bm = blockIdx.y * 128;
    const int bn = blockIdx.x * 128;

    float acc[4][4][4];
    #pragma unroll
    for (int i = 0; i < 4; ++i)
        #pragma unroll
        for (int j = 0; j < 4; ++j)
            #pragma unroll
            for (int q = 0; q < 4; ++q) acc[i][j][q] = 0.0f;

    // ---- global->register staging ----
    float4 avr[4], bvr[4];
    const int ld_row = tid >> 3;            // 0..31 (+32*i)
    const int ld_c4  = (tid & 7) * 4;       // k-col within tile

    // permuted STS bases (constant per thread; +i strides below)
    const int mr  = ld_row & 15;
    const int ki  = (tid & 7) >> 1;         // k-block 0..3
    const int chi = tid & 1;                // which 4-col half of k-block
    const int sA_base = ((ld_row >> 4) * 4 + ki) * 132
                      + (mr & 7) * 16 + ((mr >> 3) & 1) + 2 * chi;
    const int sB_base = ((ld_row >> 3) * 4 + ki) * 68
                      + (ld_row & 7) * 8 + chi;

    auto ldg = [&](int kt) {
        const float* Ak = A + (size_t)bm * GK + kt * 32 + ld_c4;
        const float* Bk = B + (size_t)bn * GK + kt * 32 + ld_c4;
        #pragma unroll
        for (int i = 0; i < 4; ++i) {
            const int row = ld_row + i * 32;
            avr[i] = *(const float4*)(Ak + (size_t)row * GK);
            if (bn + row < N)
                bvr[i] = *(const float4*)(Bk + (size_t)row * GK);
            else
                bvr[i] = make_float4(0.f, 0.f, 0.f, 0.f);
        }
    };
    auto sts = [&](int s) {
        uint32_t* dst = sm + s * STAGE_U32;
        #pragma unroll
        for (int i = 0; i < 4; ++i) {
            const int ab = sA_base + i * 1056;          // + (8 frags)*132
            dst[ab + 0]  = f2tf32(avr[i].x);            // j=0..3 -> lane+j
            dst[ab + 4]  = f2tf32(avr[i].y);
            dst[ab + 8]  = f2tf32(avr[i].z);
            dst[ab + 12] = f2tf32(avr[i].w);
            const int bb = A_REG_U32 + sB_base + i * 1088;  // + (16 frags)*68
            dst[bb + 0] = f2tf32(bvr[i].x);
            dst[bb + 2] = f2tf32(bvr[i].y);
            dst[bb + 4] = f2tf32(bvr[i].z);
            dst[bb + 6] = f2tf32(bvr[i].w);
        }
    };

    // smem->register fragment double buffer
    uint32_t afr[2][4][4], bfr[2][4][2];
    const int a_mi = warp_m >> 4;           // 0 or 4
    const int b_nb = warp_n >> 3;           // 0,4,8,12

    ldg(0);
    sts(0);

    for (int kt = 0; kt < KT; ++kt) {
        __syncthreads();                    // stage kt&1 fully written
        if (kt + 1 < KT) ldg(kt + 1);       // global prefetch overlaps MMAs

        const uint32_t* As_ = sm + (kt & 1) * STAGE_U32;
        const uint32_t* Bs_ = As_ + A_REG_U32;

        auto ldfrag = [&](int buf, int ks) {
            #pragma unroll
            for (int i = 0; i < 4; ++i) {
                const uint4 v = *(const uint4*)(
                    As_ + ((a_mi + i) * 4 + ks) * 132 + lane * 4);
                afr[buf][i][0] = v.x; afr[buf][i][1] = v.y;
                afr[buf][i][2] = v.z; afr[buf][i][3] = v.w;
            }
            #pragma unroll
            for (int j = 0; j < 4; ++j) {
                const uint2 v = *(const uint2*)(
                    Bs_ + ((b_nb + j) * 4 + ks) * 68 + lane * 2);
                bfr[buf][j][0] = v.x; bfr[buf][j][1] = v.y;
            }
        };

        ldfrag(0, 0);
        #pragma unroll
        for (int ks = 0; ks < 4; ++ks) {
            const int cur = ks & 1;
            if (ks < 3) ldfrag(cur ^ 1, ks + 1);
            #pragma unroll
            for (int i = 0; i < 4; ++i)
                #pragma unroll
                for (int j = 0; j < 4; ++j)
                    asm volatile(
                        "mma.sync.aligned.m16n8k8.row.col.f32.tf32.tf32.f32 "
                        "{%0,%1,%2,%3}, {%4,%5,%6,%7}, {%8,%9}, {%0,%1,%2,%3};"
                        : "+f"(acc[i][j][0]), "+f"(acc[i][j][1]),
                          "+f"(acc[i][j][2]), "+f"(acc[i][j][3])
                        : "r"(afr[cur][i][0]), "r"(afr[cur][i][1]),
                          "r"(afr[cur][i][2]), "r"(afr[cur][i][3]),
                          "r"(bfr[cur][j][0]), "r"(bfr[cur][j][1]));
        }

        if (kt + 1 < KT) sts((kt + 1) & 1); // write other stage (safe: last
                                            // read in iter kt-1; all threads
                                            // passed this iter's sync)
    }

    // ---- epilogue: paired f32x2 stores, guarded on N ----
    const int r  = lane >> 2;
    const int c2 = (lane & 3) * 2;
    #pragma unroll
    for (int i = 0; i < 4; ++i) {
        const int m0 = bm + warp_m + i * 16 + r;
        #pragma unroll
        for (int j = 0; j < 4; ++j) {
            const int n = bn + warp_n + j * 8 + c2;
            if (n < N) {
                const float b0v = bias ? bias[n]     : 0.0f;
                const float b1v = bias ? bias[n + 1] : 0.0f;
                float2 v0 = make_float2(acc[i][j][0] + b0v, acc[i][j][1] + b1v);
                float2 v1 = make_float2(acc[i][j][2] + b0v, acc[i][j][3] + b1v);
                *(float2*)(C + (size_t)m0 * ldc + n)       = v0;
                *(float2*)(C + (size_t)(m0 + 8) * ldc + n) = v1;
            }
        }
    }
}

// ===========================================================================
// Tiled middle stage: block = (t-tile of 64) x (b) x (h).
// ===========================================================================
#define CT 64
#define XROWS (CT + 12)

__global__ __launch_bounds__(256) void conv_gate_tiled(
    const float* __restrict__ x, const float* __restrict__ glu_b,
    const int* __restrict__ pad_p)
{
    __shared__ float xs[XROWS * R_DIM];
    __shared__ float ws[CT][8];
    __shared__ float gs[CT];

    const int t0 = blockIdx.x * CT;
    const int b  = blockIdx.y;
    const int h  = blockIdx.z;
    const int tid = threadIdx.x;
    const int pad = pad_p ? *pad_p : 6;
    const int base_c = h * R_DIM;

    for (int i = tid; i < XROWS * R_DIM; i += 256) {
        const int row = i >> 6;
        const int r   = i & 63;
        const int t   = t0 - 6 + row;
        float v = 0.0f;
        if (t >= 0 && t < T_DIM)
            v = x[((size_t)t * B_DIM + b) * C_DIM + base_c + r];
        xs[i] = v;
    }

    if (tid < CT) {
        const int t = t0 + tid;
        const int m = t * B_DIM + b;
        const float* Prow = g_P + (size_t)m * NW;
        float lg[K_DIM];
        #pragma unroll
        for (int k = 0; k < K_DIM; ++k) lg[k] = Prow[h * K_DIM + k];
        float mx = lg[0];
        #pragma unroll
        for (int k = 1; k < K_DIM; ++k) mx = fmaxf(mx, lg[k]);
        float s = 0.0f;
        #pragma unroll
        for (int k = 0; k < K_DIM; ++k) { lg[k] = expf(lg[k] - mx); s += lg[k]; }
        const float inv = 1.0f / s;
        #pragma unroll
        for (int k = 0; k < K_DIM; ++k) ws[tid][k] = lg[k] * inv;

        const float ga = Prow[112 + 2 * h]     + glu_b[2 * h];
        const float gb = Prow[112 + 2 * h + 1] + glu_b[2 * h + 1];
        gs[tid] = ga / (1.0f + expf(-gb));
    }
    __syncthreads();

    const int r  = tid & 63;
    const int tg = tid >> 6;
    const int hoff = 6 - pad;
    #pragma unroll
    for (int i = 0; i < 16; ++i) {
        const int tt = tg * 16 + i;
        float accv = 0.0f;
        #pragma unroll
        for (int k = 0; k < K_DIM; ++k)
            accv = fmaf(ws[tt][k], xs[(tt + k + hoff) * R_DIM + r], accv);
        const int m = (t0 + tt) * B_DIM + b;
        g_Y[(size_t)m * C_DIM + base_c + r] = accv * gs[tt];
    }
}

// ===========================================================================
// Launch
// ===========================================================================
extern "C" void kernel_launch(void* const* d_in, const int* in_sizes, int n_in,
                              void* d_out, int out_size)
{
    const float* x        = (const float*)d_in[0];
    const float* w_weight = (const float*)d_in[1];
    const float* glu_w    = (const float*)d_in[2];
    const float* glu_b    = (const float*)d_in[3];
    const float* out_w    = (const float*)d_in[4];
    const float* out_b    = (const float*)d_in[5];
    const int*   pad_p    = (n_in > 6) ? (const int*)d_in[6] : nullptr;

    float *P, *Y, *W1;
    cudaGetSymbolAddress((void**)&P,  g_P);
    cudaGetSymbolAddress((void**)&Y,  g_Y);
    cudaGetSymbolAddress((void**)&W1, g_W1);

    cudaFuncSetAttribute(gemm_mma_tf32,
                         cudaFuncAttributeMaxDynamicSharedMemorySize, GEMM_SMEM);

    // Concat weights for merged GEMM1 (D2D, graph-capturable)
    cudaMemcpyAsync(W1, w_weight, (size_t)112 * GK * sizeof(float),
                    cudaMemcpyDeviceToDevice, 0);
    cudaMemcpyAsync(W1 + (size_t)112 * GK, glu_w, (size_t)32 * GK * sizeof(float),
                    cudaMemcpyDeviceToDevice, 0);

    // GEMM1 (merged): P = x @ [w_weight; glu_w]^T   (N=144)
    gemm_mma_tf32<<<dim3(2, M_DIM / 128), 256, GEMM_SMEM>>>(
        x, W1, nullptr, P, NW, NW);

    // Middle stage (tiled)
    conv_gate_tiled<<<dim3(T_DIM / CT, B_DIM, H_DIM), 256>>>(x, glu_b, pad_p);

    // GEMM2: out = Y @ out_w^T + out_b   (N=1024)
    gemm_mma_tf32<<<dim3(C_DIM / 128, M_DIM / 128), 256, GEMM_SMEM>>>(
        Y, out_w, out_b, (float*)d_out, C_DIM, C_DIM);
}

// round 13
// speedup vs baseline: 1.7291x; 1.0281x over previous
#include <cuda_runtime.h>
#include <math.h>
#include <stdint.h>

// Problem shape (fixed)
#define T_DIM 2048
#define B_DIM 8
#define C_DIM 1024
#define H_DIM 16
#define K_DIM 7
#define R_DIM 64
#define M_DIM (T_DIM * B_DIM)        // 16384
#define NW    144
#define GK    1024
#define KT    (GK / 32)              // 32 k-tiles

// Scratch (__device__ globals; allocation-free rule)
__device__ float g_P [(size_t)M_DIM * NW];     // GEMM1 out: logits + glu pre-act
__device__ float g_Y [(size_t)M_DIM * C_DIM];  // conv*gate result
__device__ float g_W1[(size_t)NW * GK];        // [w_weight; glu_w] concatenated

__device__ __forceinline__ uint32_t f2tf32(float f) {
    uint32_t u;
    asm("cvt.rna.tf32.f32 %0, %1;" : "=r"(u) : "f"(f));
    return u;
}

// ===========================================================================
// tf32 mma.sync GEMM (NT), fragment-permuted smem, 64x64 WARP TILES.
// C[m*ldc+n] = sum_k A[m,k]*B[n,k] (+bias[n]).  M mult of 128, K=1024.
// Block tile 128(m) x 256(n), 256 thr = 8 warps (2m x 4n), warp 64x64,
// 4(mi) x 8(nb) m16n8k8 frags per ks, BK=32.
//
// Smem per stage (fragment-permuted):
//   A: 32 frags (mi 0..7 x ki 0..3) x 132 u32  (frag = [lane][4])
//   B: 128 frags (nb 0..31 x ki 0..3) x 68 u32 (frag = [lane][2])
// Gather: A = 4x LDS.128, B = 8x LDS.64 per ks.
// Smem traffic: ~128 B/MMA (was ~187) -> crossbar no longer binding.
// ===========================================================================
#define A_REG_U32 4224                    // 32 * 132
#define B_REG_U32 8704                    // 128 * 68
#define STAGE_U32 (A_REG_U32 + B_REG_U32) // 12928
#define GEMM_SMEM (2 * STAGE_U32 * 4)     // 103424 B dynamic

__global__ __launch_bounds__(256, 1) void gemm_mma_tf32(
    const float* __restrict__ A, const float* __restrict__ B,
    const float* __restrict__ bias, float* __restrict__ C,
    int N, int ldc)
{
    extern __shared__ uint32_t sm[];
    const int tid  = threadIdx.x;
    const int lane = tid & 31;
    const int wid  = tid >> 5;
    const int warp_m = (wid & 1) * 64;          // 0 / 64
    const int warp_n = (wid >> 1) * 64;         // 0..192
    const int bm = blockIdx.y * 128;
    const int bn = blockIdx.x * 256;

    float acc[4][8][4];
    #pragma unroll
    for (int i = 0; i < 4; ++i)
        #pragma unroll
        for (int j = 0; j < 8; ++j)
            #pragma unroll
            for (int q = 0; q < 4; ++q) acc[i][j][q] = 0.0f;

    // ---- global->register staging ----
    float4 avr[4], bvr[8];
    const int ld_row = tid >> 3;            // 0..31 (+32*i)
    const int ld_c4  = (tid & 7) * 4;       // k-col within 32

    const int mr  = ld_row & 15;
    const int ki  = (tid & 7) >> 1;         // k-block 0..3
    const int chi = tid & 1;                // 4-col half within k-block
    const int sA_base = ((ld_row >> 4) * 4 + ki) * 132
                      + (mr & 7) * 16 + ((mr >> 3) & 1) + 2 * chi;
    const int sB_base = ((ld_row >> 3) * 4 + ki) * 68
                      + (ld_row & 7) * 8 + chi;

    auto ldg = [&](int kt) {
        const float* Ak = A + (size_t)bm * GK + kt * 32 + ld_c4;
        const float* Bk = B + (size_t)bn * GK + kt * 32 + ld_c4;
        #pragma unroll
        for (int i = 0; i < 4; ++i)
            avr[i] = *(const float4*)(Ak + (size_t)(ld_row + i * 32) * GK);
        #pragma unroll
        for (int i = 0; i < 8; ++i) {
            const int row = ld_row + i * 32;
            if (bn + row < N)
                bvr[i] = *(const float4*)(Bk + (size_t)row * GK);
            else
                bvr[i] = make_float4(0.f, 0.f, 0.f, 0.f);
        }
    };
    auto sts = [&](int s) {
        uint32_t* dst = sm + s * STAGE_U32;
        #pragma unroll
        for (int i = 0; i < 4; ++i) {
            const int ab = sA_base + i * 1056;           // +8 frags * 132
            dst[ab + 0]  = f2tf32(avr[i].x);
            dst[ab + 4]  = f2tf32(avr[i].y);
            dst[ab + 8]  = f2tf32(avr[i].z);
            dst[ab + 12] = f2tf32(avr[i].w);
        }
        uint32_t* dstB = dst + A_REG_U32;
        #pragma unroll
        for (int i = 0; i < 8; ++i) {
            const int bb = sB_base + i * 1088;           // +16 frags * 68
            dstB[bb + 0] = f2tf32(bvr[i].x);
            dstB[bb + 2] = f2tf32(bvr[i].y);
            dstB[bb + 4] = f2tf32(bvr[i].z);
            dstB[bb + 6] = f2tf32(bvr[i].w);
        }
    };

    uint32_t afr[4][4], bfr[8][2];
    const int a_mi = warp_m >> 4;           // 0 or 4
    const int b_nb = warp_n >> 3;           // 0,8,16,24

    ldg(0);
    sts(0);

    for (int kt = 0; kt < KT; ++kt) {
        __syncthreads();                    // stage kt&1 fully written
        if (kt + 1 < KT) ldg(kt + 1);       // global prefetch overlaps MMAs

        const uint32_t* As_ = sm + (kt & 1) * STAGE_U32;
        const uint32_t* Bs_ = As_ + A_REG_U32;

        #pragma unroll
        for (int ks = 0; ks < 4; ++ks) {
            #pragma unroll
            for (int i = 0; i < 4; ++i) {
                const uint4 v = *(const uint4*)(
                    As_ + ((a_mi + i) * 4 + ks) * 132 + lane * 4);
                afr[i][0] = v.x; afr[i][1] = v.y;
                afr[i][2] = v.z; afr[i][3] = v.w;
            }
            #pragma unroll
            for (int j = 0; j < 8; ++j) {
                const uint2 v = *(const uint2*)(
                    Bs_ + ((b_nb + j) * 4 + ks) * 68 + lane * 2);
                bfr[j][0] = v.x; bfr[j][1] = v.y;
            }
            #pragma unroll
            for (int i = 0; i < 4; ++i)
                #pragma unroll
                for (int j = 0; j < 8; ++j)
                    asm volatile(
                        "mma.sync.aligned.m16n8k8.row.col.f32.tf32.tf32.f32 "
                        "{%0,%1,%2,%3}, {%4,%5,%6,%7}, {%8,%9}, {%0,%1,%2,%3};"
                        : "+f"(acc[i][j][0]), "+f"(acc[i][j][1]),
                          "+f"(acc[i][j][2]), "+f"(acc[i][j][3])
                        : "r"(afr[i][0]), "r"(afr[i][1]),
                          "r"(afr[i][2]), "r"(afr[i][3]),
                          "r"(bfr[j][0]), "r"(bfr[j][1]));
        }

        if (kt + 1 < KT) sts((kt + 1) & 1);
    }

    // ---- epilogue: paired f32x2 stores, guarded on N ----
    const int r  = lane >> 2;
    const int c2 = (lane & 3) * 2;
    #pragma unroll
    for (int i = 0; i < 4; ++i) {
        const int m0 = bm + warp_m + i * 16 + r;
        #pragma unroll
        for (int j = 0; j < 8; ++j) {
            const int n = bn + warp_n + j * 8 + c2;
            if (n < N) {
                const float b0v = bias ? bias[n]     : 0.0f;
                const float b1v = bias ? bias[n + 1] : 0.0f;
                float2 v0 = make_float2(acc[i][j][0] + b0v, acc[i][j][1] + b1v);
                float2 v1 = make_float2(acc[i][j][2] + b0v, acc[i][j][3] + b1v);
                *(float2*)(C + (size_t)m0 * ldc + n)       = v0;
                *(float2*)(C + (size_t)(m0 + 8) * ldc + n) = v1;
            }
        }
    }
}

// ===========================================================================
// Tiled middle stage: block = (t-tile of 64) x (b) x (h).
// ===========================================================================
#define CT 64
#define XROWS (CT + 12)

__global__ __launch_bounds__(256) void conv_gate_tiled(
    const float* __restrict__ x, const float* __restrict__ glu_b,
    const int* __restrict__ pad_p)
{
    __shared__ float xs[XROWS * R_DIM];
    __shared__ float ws[CT][8];
    __shared__ float gs[CT];

    const int t0 = blockIdx.x * CT;
    const int b  = blockIdx.y;
    const int h  = blockIdx.z;
    const int tid = threadIdx.x;
    const int pad = pad_p ? *pad_p : 6;
    const int base_c = h * R_DIM;

    for (int i = tid; i < XROWS * R_DIM; i += 256) {
        const int row = i >> 6;
        const int r   = i & 63;
        const int t   = t0 - 6 + row;
        float v = 0.0f;
        if (t >= 0 && t < T_DIM)
            v = x[((size_t)t * B_DIM + b) * C_DIM + base_c + r];
        xs[i] = v;
    }

    if (tid < CT) {
        const int t = t0 + tid;
        const int m = t * B_DIM + b;
        const float* Prow = g_P + (size_t)m * NW;
        float lg[K_DIM];
        #pragma unroll
        for (int k = 0; k < K_DIM; ++k) lg[k] = Prow[h * K_DIM + k];
        float mx = lg[0];
        #pragma unroll
        for (int k = 1; k < K_DIM; ++k) mx = fmaxf(mx, lg[k]);
        float s = 0.0f;
        #pragma unroll
        for (int k = 0; k < K_DIM; ++k) { lg[k] = expf(lg[k] - mx); s += lg[k]; }
        const float inv = 1.0f / s;
        #pragma unroll
        for (int k = 0; k < K_DIM; ++k) ws[tid][k] = lg[k] * inv;

        const float ga = Prow[112 + 2 * h]     + glu_b[2 * h];
        const float gb = Prow[112 + 2 * h + 1] + glu_b[2 * h + 1];
        gs[tid] = ga / (1.0f + expf(-gb));
    }
    __syncthreads();

    const int r  = tid & 63;
    const int tg = tid >> 6;
    const int hoff = 6 - pad;
    #pragma unroll
    for (int i = 0; i < 16; ++i) {
        const int tt = tg * 16 + i;
        float accv = 0.0f;
        #pragma unroll
        for (int k = 0; k < K_DIM; ++k)
            accv = fmaf(ws[tt][k], xs[(tt + k + hoff) * R_DIM + r], accv);
        const int m = (t0 + tt) * B_DIM + b;
        g_Y[(size_t)m * C_DIM + base_c + r] = accv * gs[tt];
    }
}

// ===========================================================================
// Launch
// ===========================================================================
extern "C" void kernel_launch(void* const* d_in, const int* in_sizes, int n_in,
                              void* d_out, int out_size)
{
    const float* x        = (const float*)d_in[0];
    const float* w_weight = (const float*)d_in[1];
    const float* glu_w    = (const float*)d_in[2];
    const float* glu_b    = (const float*)d_in[3];
    const float* out_w    = (const float*)d_in[4];
    const float* out_b    = (const float*)d_in[5];
    const int*   pad_p    = (n_in > 6) ? (const int*)d_in[6] : nullptr;

    float *P, *Y, *W1;
    cudaGetSymbolAddress((void**)&P,  g_P);
    cudaGetSymbolAddress((void**)&Y,  g_Y);
    cudaGetSymbolAddress((void**)&W1, g_W1);

    cudaFuncSetAttribute(gemm_mma_tf32,
                         cudaFuncAttributeMaxDynamicSharedMemorySize, GEMM_SMEM);

    // Concat weights for merged GEMM1 (D2D, graph-capturable)
    cudaMemcpyAsync(W1, w_weight, (size_t)112 * GK * sizeof(float),
                    cudaMemcpyDeviceToDevice, 0);
    cudaMemcpyAsync(W1 + (size_t)112 * GK, glu_w, (size_t)32 * GK * sizeof(float),
                    cudaMemcpyDeviceToDevice, 0);

    // GEMM1 (merged): P = x @ [w_weight; glu_w]^T   (N=144, one 256-wide tile)
    gemm_mma_tf32<<<dim3(1, M_DIM / 128), 256, GEMM_SMEM>>>(
        x, W1, nullptr, P, NW, NW);

    // Middle stage (tiled)
    conv_gate_tiled<<<dim3(T_DIM / CT, B_DIM, H_DIM), 256>>>(x, glu_b, pad_p);

    // GEMM2: out = Y @ out_w^T + out_b   (N=1024)
    gemm_mma_tf32<<<dim3(C_DIM / 256, M_DIM / 128), 256, GEMM_SMEM>>>(
        Y, out_w, out_b, (float*)d_out, C_DIM, C_DIM);
}

// round 14
// speedup vs baseline: 2.3682x; 1.3696x over previous
#include <cuda_runtime.h>
#include <math.h>
#include <stdint.h>

// Problem shape (fixed)
#define T_DIM 2048
#define B_DIM 8
#define C_DIM 1024
#define H_DIM 16
#define K_DIM 7
#define R_DIM 64
#define M_DIM (T_DIM * B_DIM)        // 16384
#define NW    144
#define GK    1024
#define KT    (GK / 32)              // 32 k-tiles

// Scratch (__device__ globals; allocation-free rule)
__device__ float g_P [(size_t)M_DIM * NW];     // GEMM1 out: logits + glu pre-act
__device__ float g_Y [(size_t)M_DIM * C_DIM];  // conv*gate result
__device__ float g_W1[(size_t)NW * GK];        // [w_weight; glu_w] concatenated

// pack two fp32 -> fp16x2 (lo = first elem)
__device__ __forceinline__ uint32_t pack_h2(float lo, float hi) {
    uint32_t u;
    asm("cvt.rn.f16x2.f32 %0, %1, %2;" : "=r"(u) : "f"(hi), "f"(lo));
    return u;
}

// ===========================================================================
// fp16 mma.sync GEMM (NT, fp32 accum), fragment-permuted smem, 64x64 warps.
// C[m*ldc+n] = sum_k A[m,k]*B[n,k] (+bias[n]).  M mult of 128, K=1024.
// Block 128(m) x 256(n), 256 thr = 8 warps (2m x 4n), warp 64x64,
// 4(mi) x 8(nb) m16n8k16 frags per ks, BK=32 -> 2 ks steps per k-tile.
//
// Smem per stage (fragment-permuted, fp16x2 words):
//   A: 16 frags (mi 0..7 x ks 0..1) x 132 u32  (frag = [lane][4 words])
//   B: 64 frags (nb 0..31 x ks 0..1) x 68 u32  (frag = [lane][2 words])
// Gather per ks: A = 4x LDS.128, B = 8x LDS.64.  ~halved crossbar traffic
// vs tf32 at equal FLOPs.
// ===========================================================================
#define A_REG_U32 2112                    // 16 * 132
#define B_REG_U32 4352                    // 64 * 68
#define STAGE_U32 (A_REG_U32 + B_REG_U32) // 6464
#define GEMM_SMEM (2 * STAGE_U32 * 4)     // 51712 B dynamic

__global__ __launch_bounds__(256, 1) void gemm_mma_f16(
    const float* __restrict__ A, const float* __restrict__ B,
    const float* __restrict__ bias, float* __restrict__ C,
    int N, int ldc)
{
    extern __shared__ uint32_t sm[];
    const int tid  = threadIdx.x;
    const int lane = tid & 31;
    const int wid  = tid >> 5;
    const int warp_m = (wid & 1) * 64;          // 0 / 64
    const int warp_n = (wid >> 1) * 64;         // 0..192
    const int bm = blockIdx.y * 128;
    const int bn = blockIdx.x * 256;

    float acc[4][8][4];
    #pragma unroll
    for (int i = 0; i < 4; ++i)
        #pragma unroll
        for (int j = 0; j < 8; ++j)
            #pragma unroll
            for (int q = 0; q < 4; ++q) acc[i][j][q] = 0.0f;

    // ---- global->register staging ----
    float4 avr[4], bvr[8];
    const int ld_row = tid >> 3;            // 0..31 (+32*i)
    const int ld_c4  = (tid & 7) * 4;       // k-col (fp32 elems) within 32
    // fp16 word coords for this thread's float4: kw0 = (tid&7)*2, kw1 = +1
    const int kw0 = (tid & 7) * 2;          // 0..14
    const int ksA = kw0 >> 3;               // ks block 0/1
    const int hiA = (kw0 & 7) >> 2;         // 0/1 (k-offset +8 half)
    const int cA  = kw0 & 3;                // 0 or 2 (fragment c)

    // A word addr (i-row-group term added below):
    const int sA_base = ((ld_row >> 4) * 2 + ksA) * 132
                      + ((ld_row & 7) * 4 + cA) * 4
                      + ((ld_row >> 3) & 1) + 2 * hiA;
    // B word addr:
    const int sB_base = ((ld_row >> 3) * 2 + ksA) * 68
                      + ((ld_row & 7) * 4 + cA) * 2 + hiA;

    auto ldg = [&](int kt) {
        const float* Ak = A + (size_t)bm * GK + kt * 32 + ld_c4;
        const float* Bk = B + (size_t)bn * GK + kt * 32 + ld_c4;
        #pragma unroll
        for (int i = 0; i < 4; ++i)
            avr[i] = *(const float4*)(Ak + (size_t)(ld_row + i * 32) * GK);
        #pragma unroll
        for (int i = 0; i < 8; ++i) {
            const int row = ld_row + i * 32;
            if (bn + row < N)
                bvr[i] = *(const float4*)(Bk + (size_t)row * GK);
            else
                bvr[i] = make_float4(0.f, 0.f, 0.f, 0.f);
        }
    };
    auto sts = [&](int s) {
        uint32_t* dst = sm + s * STAGE_U32;
        #pragma unroll
        for (int i = 0; i < 4; ++i) {
            const int ab = sA_base + i * 528;            // +(2 mi-frags)*2*132
            dst[ab]     = pack_h2(avr[i].x, avr[i].y);   // word kw0
            dst[ab + 4] = pack_h2(avr[i].z, avr[i].w);   // word kw0+1 (lane+1)
        }
        uint32_t* dstB = dst + A_REG_U32;
        #pragma unroll
        for (int i = 0; i < 8; ++i) {
            const int bb = sB_base + i * 544;            // +(4 nb-frags)*2*68
            dstB[bb]     = pack_h2(bvr[i].x, bvr[i].y);
            dstB[bb + 2] = pack_h2(bvr[i].z, bvr[i].w);  // lane+1
        }
    };

    uint32_t afr[4][4], bfr[8][2];
    const int a_mi = warp_m >> 4;           // 0 or 4
    const int b_nb = warp_n >> 3;           // 0,8,16,24

    ldg(0);
    sts(0);

    for (int kt = 0; kt < KT; ++kt) {
        __syncthreads();                    // stage kt&1 fully written
        if (kt + 1 < KT) ldg(kt + 1);       // global prefetch overlaps MMAs

        const uint32_t* As_ = sm + (kt & 1) * STAGE_U32;
        const uint32_t* Bs_ = As_ + A_REG_U32;

        #pragma unroll
        for (int ks = 0; ks < 2; ++ks) {
            #pragma unroll
            for (int i = 0; i < 4; ++i) {
                const uint4 v = *(const uint4*)(
                    As_ + ((a_mi + i) * 2 + ks) * 132 + lane * 4);
                afr[i][0] = v.x; afr[i][1] = v.y;
                afr[i][2] = v.z; afr[i][3] = v.w;
            }
            #pragma unroll
            for (int j = 0; j < 8; ++j) {
                const uint2 v = *(const uint2*)(
                    Bs_ + ((b_nb + j) * 2 + ks) * 68 + lane * 2);
                bfr[j][0] = v.x; bfr[j][1] = v.y;
            }
            #pragma unroll
            for (int i = 0; i < 4; ++i)
                #pragma unroll
                for (int j = 0; j < 8; ++j)
                    asm volatile(
                        "mma.sync.aligned.m16n8k16.row.col.f32.f16.f16.f32 "
                        "{%0,%1,%2,%3}, {%4,%5,%6,%7}, {%8,%9}, {%0,%1,%2,%3};"
                        : "+f"(acc[i][j][0]), "+f"(acc[i][j][1]),
                          "+f"(acc[i][j][2]), "+f"(acc[i][j][3])
                        : "r"(afr[i][0]), "r"(afr[i][1]),
                          "r"(afr[i][2]), "r"(afr[i][3]),
                          "r"(bfr[j][0]), "r"(bfr[j][1]));
        }

        if (kt + 1 < KT) sts((kt + 1) & 1);
    }

    // ---- epilogue: paired f32x2 stores, guarded on N ----
    const int r  = lane >> 2;
    const int c2 = (lane & 3) * 2;
    #pragma unroll
    for (int i = 0; i < 4; ++i) {
        const int m0 = bm + warp_m + i * 16 + r;
        #pragma unroll
        for (int j = 0; j < 8; ++j) {
            const int n = bn + warp_n + j * 8 + c2;
            if (n < N) {
                const float b0v = bias ? bias[n]     : 0.0f;
                const float b1v = bias ? bias[n + 1] : 0.0f;
                float2 v0 = make_float2(acc[i][j][0] + b0v, acc[i][j][1] + b1v);
                float2 v1 = make_float2(acc[i][j][2] + b0v, acc[i][j][3] + b1v);
                *(float2*)(C + (size_t)m0 * ldc + n)       = v0;
                *(float2*)(C + (size_t)(m0 + 8) * ldc + n) = v1;
            }
        }
    }
}

// ===========================================================================
// Tiled middle stage: block = (t-tile of 64) x (b) x (h).
// ===========================================================================
#define CT 64
#define XROWS (CT + 12)

__global__ __launch_bounds__(256) void conv_gate_tiled(
    const float* __restrict__ x, const float* __restrict__ glu_b,
    const int* __restrict__ pad_p)
{
    __shared__ float xs[XROWS * R_DIM];
    __shared__ float ws[CT][8];
    __shared__ float gs[CT];

    const int t0 = blockIdx.x * CT;
    const int b  = blockIdx.y;
    const int h  = blockIdx.z;
    const int tid = threadIdx.x;
    const int pad = pad_p ? *pad_p : 6;
    const int base_c = h * R_DIM;

    for (int i = tid; i < XROWS * R_DIM; i += 256) {
        const int row = i >> 6;
        const int r   = i & 63;
        const int t   = t0 - 6 + row;
        float v = 0.0f;
        if (t >= 0 && t < T_DIM)
            v = x[((size_t)t * B_DIM + b) * C_DIM + base_c + r];
        xs[i] = v;
    }

    if (tid < CT) {
        const int t = t0 + tid;
        const int m = t * B_DIM + b;
        const float* Prow = g_P + (size_t)m * NW;
        float lg[K_DIM];
        #pragma unroll
        for (int k = 0; k < K_DIM; ++k) lg[k] = Prow[h * K_DIM + k];
        float mx = lg[0];
        #pragma unroll
        for (int k = 1; k < K_DIM; ++k) mx = fmaxf(mx, lg[k]);
        float s = 0.0f;
        #pragma unroll
        for (int k = 0; k < K_DIM; ++k) { lg[k] = expf(lg[k] - mx); s += lg[k]; }
        const float inv = 1.0f / s;
        #pragma unroll
        for (int k = 0; k < K_DIM; ++k) ws[tid][k] = lg[k] * inv;

        const float ga = Prow[112 + 2 * h]     + glu_b[2 * h];
        const float gb = Prow[112 + 2 * h + 1] + glu_b[2 * h + 1];
        gs[tid] = ga / (1.0f + expf(-gb));
    }
    __syncthreads();

    const int r  = tid & 63;
    const int tg = tid >> 6;
    const int hoff = 6 - pad;
    #pragma unroll
    for (int i = 0; i < 16; ++i) {
        const int tt = tg * 16 + i;
        float accv = 0.0f;
        #pragma unroll
        for (int k = 0; k < K_DIM; ++k)
            accv = fmaf(ws[tt][k], xs[(tt + k + hoff) * R_DIM + r], accv);
        const int m = (t0 + tt) * B_DIM + b;
        g_Y[(size_t)m * C_DIM + base_c + r] = accv * gs[tt];
    }
}

// ===========================================================================
// Launch
// ===========================================================================
extern "C" void kernel_launch(void* const* d_in, const int* in_sizes, int n_in,
                              void* d_out, int out_size)
{
    const float* x        = (const float*)d_in[0];
    const float* w_weight = (const float*)d_in[1];
    const float* glu_w    = (const float*)d_in[2];
    const float* glu_b    = (const float*)d_in[3];
    const float* out_w    = (const float*)d_in[4];
    const float* out_b    = (const float*)d_in[5];
    const int*   pad_p    = (n_in > 6) ? (const int*)d_in[6] : nullptr;

    float *P, *Y, *W1;
    cudaGetSymbolAddress((void**)&P,  g_P);
    cudaGetSymbolAddress((void**)&Y,  g_Y);
    cudaGetSymbolAddress((void**)&W1, g_W1);

    cudaFuncSetAttribute(gemm_mma_f16,
                         cudaFuncAttributeMaxDynamicSharedMemorySize, GEMM_SMEM);

    // Concat weights for merged GEMM1 (D2D, graph-capturable)
    cudaMemcpyAsync(W1, w_weight, (size_t)112 * GK * sizeof(float),
                    cudaMemcpyDeviceToDevice, 0);
    cudaMemcpyAsync(W1 + (size_t)112 * GK, glu_w, (size_t)32 * GK * sizeof(float),
                    cudaMemcpyDeviceToDevice, 0);

    // GEMM1 (merged): P = x @ [w_weight; glu_w]^T   (N=144, one 256-wide tile)
    gemm_mma_f16<<<dim3(1, M_DIM / 128), 256, GEMM_SMEM>>>(
        x, W1, nullptr, P, NW, NW);

    // Middle stage (tiled)
    conv_gate_tiled<<<dim3(T_DIM / CT, B_DIM, H_DIM), 256>>>(x, glu_b, pad_p);

    // GEMM2: out = Y @ out_w^T + out_b   (N=1024)
    gemm_mma_f16<<<dim3(C_DIM / 256, M_DIM / 128), 256, GEMM_SMEM>>>(
        Y, out_w, out_b, (float*)d_out, C_DIM, C_DIM);
}

// round 15
// speedup vs baseline: 2.4114x; 1.0182x over previous
#include <cuda_runtime.h>
#include <math.h>
#include <stdint.h>

// Problem shape (fixed)
#define T_DIM 2048
#define B_DIM 8
#define C_DIM 1024
#define H_DIM 16
#define K_DIM 7
#define R_DIM 64
#define M_DIM (T_DIM * B_DIM)        // 16384
#define NW    144
#define GK    1024
#define KT    (GK / 32)              // 32 k-tiles

// Scratch (__device__ globals; allocation-free rule)
__device__ float g_P [(size_t)M_DIM * NW];     // GEMM1 out: logits + glu pre-act
__device__ float g_Y [(size_t)M_DIM * C_DIM];  // conv*gate result
__device__ float g_W1[(size_t)NW * GK];        // [w_weight; glu_w] concatenated

// pack two fp32 -> fp16x2 (lo = first elem)
__device__ __forceinline__ uint32_t pack_h2(float lo, float hi) {
    uint32_t u;
    asm("cvt.rn.f16x2.f32 %0, %1, %2;" : "=r"(u) : "f"(hi), "f"(lo));
    return u;
}

// ===========================================================================
// fp16 mma.sync GEMM (NT, fp32 accum), fragment-permuted smem.
// 128(m) x 128(n) block, 256 thr = 8 warps (2m x 4n), warp tile 64x32,
// 4(mi) x 4(nb) m16n8k16 frags per ks, BK=32 -> 2 ks per k-tile.
// Target 2 CTAs/SM (reg cap 128) for 4 warps/SMSP + independent barriers.
//
// Smem per stage (fp16x2 words):
//   A: 16 frags (mi 0..7 x ks 0..1) x 132 u32  (frag = [lane][4 words])
//   B: 32 frags (nb 0..15 x ks 0..1) x 68 u32  (frag = [lane][2 words])
// ===========================================================================
#define A_REG_U32 2112                    // 16 * 132
#define B_REG_U32 2176                    // 32 * 68
#define STAGE_U32 (A_REG_U32 + B_REG_U32) // 4288
#define GEMM_SMEM (2 * STAGE_U32 * 4)     // 34304 B dynamic

__global__ __launch_bounds__(256, 2) void gemm_mma_f16(
    const float* __restrict__ A, const float* __restrict__ B,
    const float* __restrict__ bias, float* __restrict__ C,
    int N, int ldc)
{
    extern __shared__ uint32_t sm[];
    const int tid  = threadIdx.x;
    const int lane = tid & 31;
    const int wid  = tid >> 5;
    const int warp_m = (wid & 1) * 64;          // 0 / 64
    const int warp_n = (wid >> 1) * 32;         // 0,32,64,96
    const int bm = blockIdx.y * 128;
    const int bn = blockIdx.x * 128;

    float acc[4][4][4];
    #pragma unroll
    for (int i = 0; i < 4; ++i)
        #pragma unroll
        for (int j = 0; j < 4; ++j)
            #pragma unroll
            for (int q = 0; q < 4; ++q) acc[i][j][q] = 0.0f;

    // ---- global->register staging ----
    float4 avr[4], bvr[4];
    const int ld_row = tid >> 3;            // 0..31 (+32*i)
    const int ld_c4  = (tid & 7) * 4;       // k-col (fp32) within 32
    const int kw0 = (tid & 7) * 2;          // fp16x2 word index 0..14
    const int ksA = kw0 >> 3;               // ks block 0/1
    const int hiA = (kw0 & 7) >> 2;         // k-offset +8 half
    const int cA  = kw0 & 3;                // fragment c (0 or 2)

    const int sA_base = ((ld_row >> 4) * 2 + ksA) * 132
                      + ((ld_row & 7) * 4 + cA) * 4
                      + ((ld_row >> 3) & 1) + 2 * hiA;
    const int sB_base = ((ld_row >> 3) * 2 + ksA) * 68
                      + ((ld_row & 7) * 4 + cA) * 2 + hiA;

    auto ldg = [&](int kt) {
        const float* Ak = A + (size_t)bm * GK + kt * 32 + ld_c4;
        const float* Bk = B + (size_t)bn * GK + kt * 32 + ld_c4;
        #pragma unroll
        for (int i = 0; i < 4; ++i) {
            const int row = ld_row + i * 32;
            avr[i] = *(const float4*)(Ak + (size_t)row * GK);
            if (bn + row < N)
                bvr[i] = *(const float4*)(Bk + (size_t)row * GK);
            else
                bvr[i] = make_float4(0.f, 0.f, 0.f, 0.f);
        }
    };
    auto sts = [&](int s) {
        uint32_t* dst = sm + s * STAGE_U32;
        uint32_t* dstB = dst + A_REG_U32;
        #pragma unroll
        for (int i = 0; i < 4; ++i) {
            const int ab = sA_base + i * 528;   // +(2 mi-frags)*2ks*132
            dst[ab]     = pack_h2(avr[i].x, avr[i].y);
            dst[ab + 4] = pack_h2(avr[i].z, avr[i].w);  // lane+1 word
            const int bb = sB_base + i * 544;   // +(4 nb-frags)*2ks*68
            dstB[bb]     = pack_h2(bvr[i].x, bvr[i].y);
            dstB[bb + 2] = pack_h2(bvr[i].z, bvr[i].w);
        }
    };

    uint32_t afr[4][4], bfr[4][2];
    const int a_mi = warp_m >> 4;           // 0 or 4
    const int b_nb = warp_n >> 3;           // 0,4,8,12

    ldg(0);
    sts(0);

    for (int kt = 0; kt < KT; ++kt) {
        __syncthreads();                    // stage kt&1 fully written
        if (kt + 1 < KT) ldg(kt + 1);       // global prefetch overlaps MMAs

        const uint32_t* As_ = sm + (kt & 1) * STAGE_U32;
        const uint32_t* Bs_ = As_ + A_REG_U32;

        #pragma unroll
        for (int ks = 0; ks < 2; ++ks) {
            #pragma unroll
            for (int i = 0; i < 4; ++i) {
                const uint4 v = *(const uint4*)(
                    As_ + ((a_mi + i) * 2 + ks) * 132 + lane * 4);
                afr[i][0] = v.x; afr[i][1] = v.y;
                afr[i][2] = v.z; afr[i][3] = v.w;
            }
            #pragma unroll
            for (int j = 0; j < 4; ++j) {
                const uint2 v = *(const uint2*)(
                    Bs_ + ((b_nb + j) * 2 + ks) * 68 + lane * 2);
                bfr[j][0] = v.x; bfr[j][1] = v.y;
            }
            #pragma unroll
            for (int i = 0; i < 4; ++i)
                #pragma unroll
                for (int j = 0; j < 4; ++j)
                    asm volatile(
                        "mma.sync.aligned.m16n8k16.row.col.f32.f16.f16.f32 "
                        "{%0,%1,%2,%3}, {%4,%5,%6,%7}, {%8,%9}, {%0,%1,%2,%3};"
                        : "+f"(acc[i][j][0]), "+f"(acc[i][j][1]),
                          "+f"(acc[i][j][2]), "+f"(acc[i][j][3])
                        : "r"(afr[i][0]), "r"(afr[i][1]),
                          "r"(afr[i][2]), "r"(afr[i][3]),
                          "r"(bfr[j][0]), "r"(bfr[j][1]));
        }

        if (kt + 1 < KT) sts((kt + 1) & 1);
    }

    // ---- epilogue: paired f32x2 stores, guarded on N ----
    const int r  = lane >> 2;
    const int c2 = (lane & 3) * 2;
    #pragma unroll
    for (int i = 0; i < 4; ++i) {
        const int m0 = bm + warp_m + i * 16 + r;
        #pragma unroll
        for (int j = 0; j < 4; ++j) {
            const int n = bn + warp_n + j * 8 + c2;
            if (n < N) {
                const float b0v = bias ? bias[n]     : 0.0f;
                const float b1v = bias ? bias[n + 1] : 0.0f;
                float2 v0 = make_float2(acc[i][j][0] + b0v, acc[i][j][1] + b1v);
                float2 v1 = make_float2(acc[i][j][2] + b0v, acc[i][j][3] + b1v);
                *(float2*)(C + (size_t)m0 * ldc + n)       = v0;
                *(float2*)(C + (size_t)(m0 + 8) * ldc + n) = v1;
            }
        }
    }
}

// ===========================================================================
// Tiled middle stage: block = (t-tile of 64) x (b) x (h).
// ===========================================================================
#define CT 64
#define XROWS (CT + 12)

__global__ __launch_bounds__(256) void conv_gate_tiled(
    const float* __restrict__ x, const float* __restrict__ glu_b,
    const int* __restrict__ pad_p)
{
    __shared__ float xs[XROWS * R_DIM];
    __shared__ float ws[CT][8];
    __shared__ float gs[CT];

    const int t0 = blockIdx.x * CT;
    const int b  = blockIdx.y;
    const int h  = blockIdx.z;
    const int tid = threadIdx.x;
    const int pad = pad_p ? *pad_p : 6;
    const int base_c = h * R_DIM;

    for (int i = tid; i < XROWS * R_DIM; i += 256) {
        const int row = i >> 6;
        const int r   = i & 63;
        const int t   = t0 - 6 + row;
        float v = 0.0f;
        if (t >= 0 && t < T_DIM)
            v = x[((size_t)t * B_DIM + b) * C_DIM + base_c + r];
        xs[i] = v;
    }

    if (tid < CT) {
        const int t = t0 + tid;
        const int m = t * B_DIM + b;
        const float* Prow = g_P + (size_t)m * NW;
        float lg[K_DIM];
        #pragma unroll
        for (int k = 0; k < K_DIM; ++k) lg[k] = Prow[h * K_DIM + k];
        float mx = lg[0];
        #pragma unroll
        for (int k = 1; k < K_DIM; ++k) mx = fmaxf(mx, lg[k]);
        float s = 0.0f;
        #pragma unroll
        for (int k = 0; k < K_DIM; ++k) { lg[k] = expf(lg[k] - mx); s += lg[k]; }
        const float inv = 1.0f / s;
        #pragma unroll
        for (int k = 0; k < K_DIM; ++k) ws[tid][k] = lg[k] * inv;

        const float ga = Prow[112 + 2 * h]     + glu_b[2 * h];
        const float gb = Prow[112 + 2 * h + 1] + glu_b[2 * h + 1];
        gs[tid] = ga / (1.0f + expf(-gb));
    }
    __syncthreads();

    const int r  = tid & 63;
    const int tg = tid >> 6;
    const int hoff = 6 - pad;
    #pragma unroll
    for (int i = 0; i < 16; ++i) {
        const int tt = tg * 16 + i;
        float accv = 0.0f;
        #pragma unroll
        for (int k = 0; k < K_DIM; ++k)
            accv = fmaf(ws[tt][k], xs[(tt + k + hoff) * R_DIM + r], accv);
        const int m = (t0 + tt) * B_DIM + b;
        g_Y[(size_t)m * C_DIM + base_c + r] = accv * gs[tt];
    }
}

// ===========================================================================
// Launch
// ===========================================================================
extern "C" void kernel_launch(void* const* d_in, const int* in_sizes, int n_in,
                              void* d_out, int out_size)
{
    const float* x        = (const float*)d_in[0];
    const float* w_weight = (const float*)d_in[1];
    const float* glu_w    = (const float*)d_in[2];
    const float* glu_b    = (const float*)d_in[3];
    const float* out_w    = (const float*)d_in[4];
    const float* out_b    = (const float*)d_in[5];
    const int*   pad_p    = (n_in > 6) ? (const int*)d_in[6] : nullptr;

    float *P, *Y, *W1;
    cudaGetSymbolAddress((void**)&P,  g_P);
    cudaGetSymbolAddress((void**)&Y,  g_Y);
    cudaGetSymbolAddress((void**)&W1, g_W1);

    cudaFuncSetAttribute(gemm_mma_f16,
                         cudaFuncAttributeMaxDynamicSharedMemorySize, GEMM_SMEM);

    // Concat weights for merged GEMM1 (D2D, graph-capturable)
    cudaMemcpyAsync(W1, w_weight, (size_t)112 * GK * sizeof(float),
                    cudaMemcpyDeviceToDevice, 0);
    cudaMemcpyAsync(W1 + (size_t)112 * GK, glu_w, (size_t)32 * GK * sizeof(float),
                    cudaMemcpyDeviceToDevice, 0);

    // GEMM1 (merged): P = x @ [w_weight; glu_w]^T   (N=144 -> 2 n-tiles)
    gemm_mma_f16<<<dim3(2, M_DIM / 128), 256, GEMM_SMEM>>>(
        x, W1, nullptr, P, NW, NW);

    // Middle stage (tiled)
    conv_gate_tiled<<<dim3(T_DIM / CT, B_DIM, H_DIM), 256>>>(x, glu_b, pad_p);

    // GEMM2: out = Y @ out_w^T + out_b   (N=1024)
    gemm_mma_f16<<<dim3(C_DIM / 128, M_DIM / 128), 256, GEMM_SMEM>>>(
        Y, out_w, out_b, (float*)d_out, C_DIM, C_DIM);
}